// round 4
// baseline (speedup 1.0000x reference)
#include <cuda_runtime.h>
#include <cuda_bf16.h>
#include <cstdint>

// Problem constants (fixed by the dataset)
#define B_SZ   1024
#define NIN    2048
#define NOUT   2048
#define NC     10
#define TSTEPS 10

#define DECAY  0.2f
#define THRESH 0.5f
#define TD     0.1f   // THRESH * DECAY

// Scratch: h = x @ W_enc^T  (8 MB) and per-row loss partials.
__device__ float g_h[B_SZ * NOUT];
__device__ float g_lossPartial[B_SZ];

// ---------------------------------------------------------------------------
// Kernel 1: fp32 GEMM  C[M,N] = A[M,K] * B[N,K]^T   (both K-contiguous)
// 128x128 CTA tile, BK=16, 256 threads, 8x8 per-thread microtile.
// ---------------------------------------------------------------------------
#define BM 128
#define BN 128
#define BK 16

__global__ __launch_bounds__(256, 1)
void gemm_f32_nt(const float* __restrict__ A, const float* __restrict__ Bm,
                 float* __restrict__ C, int M, int N, int K)
{
    __shared__ float As[BK][BM + 4];
    __shared__ float Bs[BK][BN + 4];

    const int tid = threadIdx.x;
    const int tx = tid & 15;         // 0..15 -> N microtile
    const int ty = tid >> 4;         // 0..15 -> M microtile
    const int bm = blockIdx.y * BM;
    const int bn = blockIdx.x * BN;

    const float* Ab = A + (size_t)bm * K;
    const float* Bb = Bm + (size_t)bn * K;

    float acc[8][8];
#pragma unroll
    for (int i = 0; i < 8; i++)
#pragma unroll
        for (int j = 0; j < 8; j++) acc[i][j] = 0.0f;

    for (int kt = 0; kt < K; kt += BK) {
        // Load 128x16 tiles of A and B (2 float4 per thread each), store transposed.
#pragma unroll
        for (int l = 0; l < 2; l++) {
            int idx = tid + l * 256;          // 0..511
            int row = idx >> 2;               // 0..127
            int cv  = (idx & 3) << 2;         // 0,4,8,12
            float4 va = *(const float4*)(Ab + (size_t)row * K + kt + cv);
            As[cv + 0][row] = va.x; As[cv + 1][row] = va.y;
            As[cv + 2][row] = va.z; As[cv + 3][row] = va.w;
            float4 vb = *(const float4*)(Bb + (size_t)row * K + kt + cv);
            Bs[cv + 0][row] = vb.x; Bs[cv + 1][row] = vb.y;
            Bs[cv + 2][row] = vb.z; Bs[cv + 3][row] = vb.w;
        }
        __syncthreads();

#pragma unroll
        for (int k = 0; k < BK; k++) {
            float a[8], b[8];
#pragma unroll
            for (int i = 0; i < 4; i++) {
                a[i]     = As[k][ty * 4 + i];
                a[4 + i] = As[k][64 + ty * 4 + i];
                b[i]     = Bs[k][tx * 4 + i];
                b[4 + i] = Bs[k][64 + tx * 4 + i];
            }
#pragma unroll
            for (int i = 0; i < 8; i++)
#pragma unroll
                for (int j = 0; j < 8; j++)
                    acc[i][j] = fmaf(a[i], b[j], acc[i][j]);
        }
        __syncthreads();
    }

#pragma unroll
    for (int i = 0; i < 8; i++) {
        int r = bm + ((i < 4) ? (ty * 4 + i) : (64 + ty * 4 + i - 4));
#pragma unroll
        for (int j = 0; j < 8; j++) {
            int c = bn + ((j < 4) ? (tx * 4 + j) : (64 + tx * 4 + j - 4));
            C[(size_t)r * N + c] = acc[i][j];
        }
    }
}

// ---------------------------------------------------------------------------
// Kernel 2: full SNN recurrence. One CTA per batch row; 256 threads.
// Each thread owns 8 neurons (j = tid + 256*i). W_dec staged in SMEM.
// Threads 0..9 own the decoder class state (ym, ys, loss).
// ---------------------------------------------------------------------------
__global__ __launch_bounds__(256)
void snn_steps(const float* __restrict__ h, const float* __restrict__ Wdec,
               const float* __restrict__ yoh, float* __restrict__ out,
               float* __restrict__ lossPartial)
{
    extern __shared__ float smem[];
    float* sW  = smem;               // NC * NOUT floats (80 KB)
    float* red = smem + NC * NOUT;   // 8 warps * NC floats

    const int b = blockIdx.x;
    const int tid = threadIdx.x;
    const int warp = tid >> 5, lane = tid & 31;

    for (int i = tid; i < NC * NOUT; i += 256) sW[i] = Wdec[i];

    float hreg[8], mem[8], spk[8];
#pragma unroll
    for (int i = 0; i < 8; i++) {
        hreg[i] = h[(size_t)b * NOUT + tid + 256 * i];
        mem[i] = 0.0f; spk[i] = 0.0f;
    }

    float ym = 0.0f, ys = 0.0f, yo = 0.0f, lossc = 0.0f;
    if (tid < NC) yo = yoh[b * NC + tid];
    __syncthreads();

    for (int t = 0; t < TSTEPS; t++) {
        float acc[NC];
#pragma unroll
        for (int c = 0; c < NC; c++) acc[c] = 0.0f;

#pragma unroll
        for (int i = 0; i < 8; i++) {
            mem[i] = mem[i] * DECAY + hreg[i] - spk[i] * TD;
            spk[i] = (mem[i] > THRESH) ? 1.0f : 0.0f;
            int j = tid + 256 * i;
            out[(size_t)t * (B_SZ * NOUT) + (size_t)b * NOUT + j] = spk[i];
#pragma unroll
            for (int c = 0; c < NC; c++)
                acc[c] = fmaf(spk[i], sW[c * NOUT + j], acc[c]);
        }

        // intra-warp reduce each class
#pragma unroll
        for (int c = 0; c < NC; c++) {
#pragma unroll
            for (int o = 16; o > 0; o >>= 1)
                acc[c] += __shfl_down_sync(0xffffffffu, acc[c], o);
        }
        if (lane == 0) {
#pragma unroll
            for (int c = 0; c < NC; c++) red[warp * NC + c] = acc[c];
        }
        __syncthreads();

        if (tid < NC) {
            float tot = 0.0f;
#pragma unroll
            for (int w = 0; w < 8; w++) tot += red[w * NC + tid];
            ym = ym * DECAY + tot - ys * TD;
            ys = (ym > THRESH) ? 1.0f : 0.0f;
            float d = ys - yo;
            lossc = fmaf(d, d, lossc);
        }
        __syncthreads();   // protect red before next step reuses it
    }

    if (tid < NC) red[tid] = lossc;
    __syncthreads();
    if (tid == 0) {
        float s = 0.0f;
#pragma unroll
        for (int c = 0; c < NC; c++) s += red[c];
        lossPartial[b] = s;
    }
}

// ---------------------------------------------------------------------------
// Kernel 3: reduce per-row loss partials -> out[out_size-1]
// ---------------------------------------------------------------------------
__global__ void loss_reduce(const float* __restrict__ lp, float* __restrict__ out,
                            int out_size)
{
    __shared__ float s[256];
    float v = 0.0f;
    for (int i = threadIdx.x; i < B_SZ; i += 256) v += lp[i];
    s[threadIdx.x] = v;
    __syncthreads();
    for (int o = 128; o > 0; o >>= 1) {
        if (threadIdx.x < o) s[threadIdx.x] += s[threadIdx.x + o];
        __syncthreads();
    }
    if (threadIdx.x == 0)
        out[out_size - 1] = s[0] / (float)(B_SZ * NC);  // mean over [B, NC], summed over T
}

// ---------------------------------------------------------------------------
extern "C" void kernel_launch(void* const* d_in, const int* in_sizes, int n_in,
                              void* d_out, int out_size)
{
    const float* x     = (const float*)d_in[0];   // [1024, 2048]
    const float* W_enc = (const float*)d_in[1];   // [2048, 2048]
    const float* W_dec = (const float*)d_in[2];   // [10, 2048]
    const float* y_oh  = (const float*)d_in[3];   // [1024, 10]
    float* out = (float*)d_out;

    float* h;
    cudaGetSymbolAddress((void**)&h, g_h);
    float* lp;
    cudaGetSymbolAddress((void**)&lp, g_lossPartial);

    // GEMM: h = x @ W_enc^T
    dim3 ggrid(NOUT / BN, B_SZ / BM);
    gemm_f32_nt<<<ggrid, 256>>>(x, W_enc, h, B_SZ, NOUT, NIN);

    // Recurrence (needs ~82 KB dynamic SMEM)
    int smem_bytes = (NC * NOUT + 8 * NC) * (int)sizeof(float);
    cudaFuncSetAttribute(snn_steps, cudaFuncAttributeMaxDynamicSharedMemorySize,
                         smem_bytes);
    snn_steps<<<B_SZ, 256, smem_bytes>>>(h, W_dec, y_oh, out, lp);

    // Final loss scalar
    loss_reduce<<<1, 256>>>(lp, out, out_size);
}

// round 5
// speedup vs baseline: 1.3325x; 1.3325x over previous
#include <cuda_runtime.h>
#include <cuda_bf16.h>
#include <cstdint>

// Problem constants (fixed by the dataset)
#define B_SZ   1024
#define NIN    2048
#define NOUT   2048
#define NC     10
#define TSTEPS 10

#define DECAY  0.2f
#define THRESH 0.5f
#define TD     0.1f   // THRESH * DECAY

// Scratch: h = x @ W_enc^T  (8 MB) and per-row loss partials.
__device__ float g_h[B_SZ * NOUT];
__device__ float g_lossPartial[B_SZ];

// ---------------------------------------------------------------------------
// Packed fp32x2 helpers (Blackwell: fma.rn.f32x2 — 2 IEEE fp32 FMAs per issue)
// ---------------------------------------------------------------------------
__device__ __forceinline__ unsigned long long pack2(float lo, float hi) {
    unsigned long long d;
    asm("mov.b64 %0, {%1, %2};" : "=l"(d)
        : "r"(__float_as_int(lo)), "r"(__float_as_int(hi)));
    return d;
}
__device__ __forceinline__ void unpack2(unsigned long long v, float& lo, float& hi) {
    int a, b;
    asm("mov.b64 {%0, %1}, %2;" : "=r"(a), "=r"(b) : "l"(v));
    lo = __int_as_float(a); hi = __int_as_float(b);
}
__device__ __forceinline__ unsigned long long ffma2(unsigned long long a,
                                                    unsigned long long b,
                                                    unsigned long long c) {
    unsigned long long d;
    asm("fma.rn.f32x2 %0, %1, %2, %3;" : "=l"(d) : "l"(a), "l"(b), "l"(c));
    return d;
}
__device__ __forceinline__ unsigned long long fadd2(unsigned long long a,
                                                    unsigned long long b) {
    unsigned long long d;
    asm("add.rn.f32x2 %0, %1, %2;" : "=l"(d) : "l"(a), "l"(b));
    return d;
}

// ---------------------------------------------------------------------------
// Kernel 1: fp32 GEMM  C[M,N] = A[M,K] * B[N,K]^T  via packed f32x2 FMA.
// 128x64 CTA tile, BK=16, 256 threads, 8x4 per-thread microtile
// (held as 4x4 f32x2 accumulators, row-pairs packed).
// Double-buffered SMEM with register prefetch; 1 syncthreads per K-tile.
// ---------------------------------------------------------------------------
#define BM 128
#define BN 64
#define BK 16

__global__ __launch_bounds__(256, 2)
void gemm_f32x2_nt(const float* __restrict__ A, const float* __restrict__ Bm,
                   float* __restrict__ C)
{
    __shared__ float As[2][BK][BM + 4];
    __shared__ float Bs[2][BK][BN + 4];

    const int tid = threadIdx.x;
    const int tx = tid & 15;          // 0..15 -> N microtile (4 cols)
    const int ty = tid >> 4;          // 0..15 -> M microtile (8 rows)
    const int bm = blockIdx.y * BM;
    const int bn = blockIdx.x * BN;

    const float* Ab = A + (size_t)bm * NIN;
    const float* Bb = Bm + (size_t)bn * NIN;

    // Global->SMEM mapping: A tile 128x16 = 2 float4/thread, B tile 64x16 = 1.
    const int lrow = tid >> 2;            // 0..63
    const int lcol = (tid & 3) << 2;      // 0,4,8,12

    unsigned long long acc[4][4];
#pragma unroll
    for (int i = 0; i < 4; i++)
#pragma unroll
        for (int j = 0; j < 4; j++) acc[i][j] = 0ull;

    // Prologue: load K-tile 0, stage into buffer 0.
    float4 pa0 = *(const float4*)(Ab + (size_t)lrow * NIN + lcol);
    float4 pa1 = *(const float4*)(Ab + (size_t)(lrow + 64) * NIN + lcol);
    float4 pb  = *(const float4*)(Bb + (size_t)lrow * NIN + lcol);
#pragma unroll
    for (int v = 0; v < 4; v++) {
        As[0][lcol + v][lrow]      = (&pa0.x)[v];
        As[0][lcol + v][lrow + 64] = (&pa1.x)[v];
        Bs[0][lcol + v][lrow]      = (&pb.x)[v];
    }
    __syncthreads();

    const int NT = NIN / BK;   // 128
    for (int t = 0; t < NT; t++) {
        const int p = t & 1;
        // Prefetch next K-tile into registers (overlaps with compute).
        if (t + 1 < NT) {
            const int ko = (t + 1) * BK;
            pa0 = *(const float4*)(Ab + (size_t)lrow * NIN + ko + lcol);
            pa1 = *(const float4*)(Ab + (size_t)(lrow + 64) * NIN + ko + lcol);
            pb  = *(const float4*)(Bb + (size_t)lrow * NIN + ko + lcol);
        }

#pragma unroll
        for (int k = 0; k < BK; k++) {
            float4 va0 = *(const float4*)&As[p][k][ty * 8];
            float4 va1 = *(const float4*)&As[p][k][ty * 8 + 4];
            float4 vb  = *(const float4*)&Bs[p][k][tx * 4];
            unsigned long long a2[4], b2[4];
            a2[0] = pack2(va0.x, va0.y); a2[1] = pack2(va0.z, va0.w);
            a2[2] = pack2(va1.x, va1.y); a2[3] = pack2(va1.z, va1.w);
            b2[0] = pack2(vb.x, vb.x);   b2[1] = pack2(vb.y, vb.y);
            b2[2] = pack2(vb.z, vb.z);   b2[3] = pack2(vb.w, vb.w);
#pragma unroll
            for (int i = 0; i < 4; i++)
#pragma unroll
                for (int j = 0; j < 4; j++)
                    acc[i][j] = ffma2(a2[i], b2[j], acc[i][j]);
        }

        if (t + 1 < NT) {
            const int q = p ^ 1;
#pragma unroll
            for (int v = 0; v < 4; v++) {
                As[q][lcol + v][lrow]      = (&pa0.x)[v];
                As[q][lcol + v][lrow + 64] = (&pa1.x)[v];
                Bs[q][lcol + v][lrow]      = (&pb.x)[v];
            }
            __syncthreads();
        }
    }

    // Epilogue: unpack row-pairs, store as float4 per row.
#pragma unroll
    for (int i = 0; i < 4; i++) {
        float4 r0, r1;
        unpack2(acc[i][0], r0.x, r1.x);
        unpack2(acc[i][1], r0.y, r1.y);
        unpack2(acc[i][2], r0.z, r1.z);
        unpack2(acc[i][3], r0.w, r1.w);
        const size_t row0 = (size_t)(bm + ty * 8 + 2 * i) * NOUT + bn + tx * 4;
        *(float4*)&C[row0]        = r0;
        *(float4*)&C[row0 + NOUT] = r1;
    }
}

// ---------------------------------------------------------------------------
// Kernel 2: full SNN recurrence. One CTA per batch row; 256 threads.
// Each thread owns 8 neurons (j = tid + 256*i). W_dec held in REGISTERS
// (40 packed f32x2 per thread), no big SMEM -> no LDS crossbar bottleneck.
// Decoder partials via f32x2 FMA; reduction via 64-bit shuffles + add.f32x2.
// ---------------------------------------------------------------------------
__global__ __launch_bounds__(256)
void snn_steps(const float* __restrict__ h, const float* __restrict__ Wdec,
               const float* __restrict__ yoh, float* __restrict__ out,
               float* __restrict__ lossPartial)
{
    __shared__ float red[8 * NC + NC];   // per-warp partials + final scratch

    const int b = blockIdx.x;
    const int tid = threadIdx.x;
    const int warp = tid >> 5, lane = tid & 31;

    // Load decoder weights into registers, packed by class pair:
    // w2[i][c] = { Wdec[2c][j], Wdec[2c+1][j] },  j = tid + 256*i
    unsigned long long w2[8][5];
#pragma unroll
    for (int i = 0; i < 8; i++) {
        const int j = tid + 256 * i;
#pragma unroll
        for (int c = 0; c < 5; c++)
            w2[i][c] = pack2(Wdec[(2 * c) * NOUT + j],
                             Wdec[(2 * c + 1) * NOUT + j]);
    }

    float hreg[8], mem[8], spk[8];
#pragma unroll
    for (int i = 0; i < 8; i++) {
        hreg[i] = h[(size_t)b * NOUT + tid + 256 * i];
        mem[i] = 0.0f; spk[i] = 0.0f;
    }

    float ym = 0.0f, ys = 0.0f, yo = 0.0f, lossc = 0.0f;
    if (tid < NC) yo = yoh[b * NC + tid];
    __syncthreads();

    for (int t = 0; t < TSTEPS; t++) {
        unsigned long long acc2[5];
#pragma unroll
        for (int c = 0; c < 5; c++) acc2[c] = 0ull;

#pragma unroll
        for (int i = 0; i < 8; i++) {
            mem[i] = mem[i] * DECAY + hreg[i] - spk[i] * TD;
            spk[i] = (mem[i] > THRESH) ? 1.0f : 0.0f;
            const int j = tid + 256 * i;
            out[(size_t)t * (B_SZ * NOUT) + (size_t)b * NOUT + j] = spk[i];
            const unsigned long long s2 = pack2(spk[i], spk[i]);
#pragma unroll
            for (int c = 0; c < 5; c++)
                acc2[c] = ffma2(s2, w2[i][c], acc2[c]);
        }

        // intra-warp tree reduction on packed pairs
#pragma unroll
        for (int c = 0; c < 5; c++) {
#pragma unroll
            for (int o = 16; o > 0; o >>= 1) {
                unsigned long long other =
                    __shfl_down_sync(0xffffffffu, acc2[c], o);
                acc2[c] = fadd2(acc2[c], other);
            }
        }
        if (lane == 0) {
#pragma unroll
            for (int c = 0; c < 5; c++) {
                float lo, hi;
                unpack2(acc2[c], lo, hi);
                red[warp * NC + 2 * c]     = lo;
                red[warp * NC + 2 * c + 1] = hi;
            }
        }
        __syncthreads();

        if (tid < NC) {
            float tot = 0.0f;
#pragma unroll
            for (int w = 0; w < 8; w++) tot += red[w * NC + tid];
            ym = ym * DECAY + tot - ys * TD;
            ys = (ym > THRESH) ? 1.0f : 0.0f;
            const float d = ys - yo;
            lossc = fmaf(d, d, lossc);
        }
        __syncthreads();   // protect red before next step reuses it
    }

    if (tid < NC) red[8 * NC + tid] = lossc;
    __syncthreads();
    if (tid == 0) {
        float s = 0.0f;
#pragma unroll
        for (int c = 0; c < NC; c++) s += red[8 * NC + c];
        lossPartial[b] = s;
    }
}

// ---------------------------------------------------------------------------
// Kernel 3: reduce per-row loss partials -> out[out_size-1]
// ---------------------------------------------------------------------------
__global__ void loss_reduce(const float* __restrict__ lp, float* __restrict__ out,
                            int out_size)
{
    __shared__ float s[256];
    float v = 0.0f;
    for (int i = threadIdx.x; i < B_SZ; i += 256) v += lp[i];
    s[threadIdx.x] = v;
    __syncthreads();
    for (int o = 128; o > 0; o >>= 1) {
        if (threadIdx.x < o) s[threadIdx.x] += s[threadIdx.x + o];
        __syncthreads();
    }
    if (threadIdx.x == 0)
        out[out_size - 1] = s[0] / (float)(B_SZ * NC);  // mean over [B, NC], summed over T
}

// ---------------------------------------------------------------------------
extern "C" void kernel_launch(void* const* d_in, const int* in_sizes, int n_in,
                              void* d_out, int out_size)
{
    const float* x     = (const float*)d_in[0];   // [1024, 2048]
    const float* W_enc = (const float*)d_in[1];   // [2048, 2048]
    const float* W_dec = (const float*)d_in[2];   // [10, 2048]
    const float* y_oh  = (const float*)d_in[3];   // [1024, 10]
    float* out = (float*)d_out;

    float* h;
    cudaGetSymbolAddress((void**)&h, g_h);
    float* lp;
    cudaGetSymbolAddress((void**)&lp, g_lossPartial);

    // GEMM: h = x @ W_enc^T   (grid = 32 x 8 = 256 CTAs)
    dim3 ggrid(NOUT / BN, B_SZ / BM);
    gemm_f32x2_nt<<<ggrid, 256>>>(x, W_enc, h);

    // Recurrence
    snn_steps<<<B_SZ, 256>>>(h, W_dec, y_oh, out, lp);

    // Final loss scalar
    loss_reduce<<<1, 256>>>(lp, out, out_size);
}